// round 5
// baseline (speedup 1.0000x reference)
#include <cuda_runtime.h>

// Division-free scaled downward Levinson as a CLIP DETECTOR, TWO ROWS PER
// THREAD packed into f32x2 (FFMA2): every inner-loop fma.rn.f32x2 updates
// both rows at once. If no |k| > 1 (BOUND = 1-1e-16 rounds to 1.0f), the
// PARCOR round trip is the identity and out == in, which was already
// streamed to GMEM during staging. Clipped/degenerate rows take the exact
// textbook path in a __noinline__ fixup (keeps hot-path registers low).

#define M 24
#define ROW 25
#define THREADS 128
#define ROWS_PER_BLK 256                 // 2 rows per thread
#define ELEMS (ROWS_PER_BLK * ROW)       // 6400 floats
#define VECS  (ELEMS / 4)                // 1600 float4

typedef unsigned long long u64;

__device__ __forceinline__ u64 pk2(float lo, float hi) {
    u64 d;
    asm("mov.b64 %0, {%1, %2};" : "=l"(d)
        : "r"(__float_as_uint(lo)), "r"(__float_as_uint(hi)));
    return d;
}
__device__ __forceinline__ void upk2(u64 d, float& lo, float& hi) {
    unsigned a, b;
    asm("mov.b64 {%0, %1}, %2;" : "=r"(a), "=r"(b) : "l"(d));
    lo = __uint_as_float(a); hi = __uint_as_float(b);
}
__device__ __forceinline__ u64 fma2(u64 a, u64 b, u64 c) {
    u64 r;
    asm("fma.rn.f32x2 %0, %1, %2, %3;" : "=l"(r) : "l"(a), "l"(b), "l"(c));
    return r;
}

// Exact per-row path: downward recursion with true divides, clamp, upward
// recursion, overwrite out row. Rare to nonexistent for this data.
__device__ __noinline__ void fixup_row(const float* __restrict__ srow,
                                       float* __restrict__ orow)
{
    float c[M];
    #pragma unroll
    for (int i = 0; i < M; ++i) c[i] = srow[i + 1];

    #pragma unroll
    for (int m = M; m >= 2; --m) {
        float k   = c[m - 1];
        float inv = __fdividef(1.0f, 1.0f - k * k);
        #pragma unroll
        for (int i = 0; 2 * i <= m - 2; ++i) {
            int j = m - 2 - i;
            float ci = c[i], cj = c[j];
            if (i < j) {
                c[i] = fmaf(-k, cj, ci) * inv;
                c[j] = fmaf(-k, ci, cj) * inv;
            } else {
                c[i] = fmaf(-k, ci, ci) * inv;
            }
        }
    }
    #pragma unroll
    for (int i = 0; i < M; ++i)
        c[i] = fminf(fmaxf(c[i], -1.0f), 1.0f);

    #pragma unroll
    for (int m = 2; m <= M; ++m) {
        float km = c[m - 1];
        #pragma unroll
        for (int i = 0; 2 * i <= m - 2; ++i) {
            int j = m - 2 - i;
            float ci = c[i], cj = c[j];
            if (i < j) {
                c[i] = fmaf(km, cj, ci);
                c[j] = fmaf(km, ci, cj);
            } else {
                c[i] = fmaf(km, ci, ci);
            }
        }
    }
    #pragma unroll
    for (int i = 0; i < M; ++i) orow[i + 1] = c[i];
    // orow[0] (gain K) already correct from the bulk copy
}

__global__ __launch_bounds__(THREADS)
void lpc_stability_kernel(const float* __restrict__ in, float* __restrict__ out, int B)
{
    __shared__ float s[ELEMS];

    const int tid   = threadIdx.x;
    const int rbase = blockIdx.x * ROWS_PER_BLK;
    const long long gbase = (long long)blockIdx.x * ELEMS;
    const int nrows = min(ROWS_PER_BLK, B - rbase);

    if (nrows == ROWS_PER_BLK) {
        const float4* __restrict__ g4 = (const float4*)(in + gbase);
        float4* __restrict__ o4 = (float4*)(out + gbase);
        float4* s4 = (float4*)s;
        #pragma unroll
        for (int i = 0; i < 13; ++i) {
            int idx = tid + i * THREADS;
            if (idx < VECS) {
                float4 v = g4[idx];
                o4[idx] = v;       // commit output immediately (common path)
                s4[idx] = v;       // stage for the detector
            }
        }
    } else {
        int nelems = nrows * ROW;
        for (int idx = tid; idx < nelems; idx += THREADS) {
            float v = in[gbase + idx];
            out[gbase + idx] = v;
            s[idx] = v;
        }
    }
    __syncthreads();   // orders bulk stores before fixup stores; smem ready

    const int  rA = tid;
    const int  rB = tid + THREADS;
    const bool vA = rA < nrows;
    const bool vB = rB < nrows;
    const float* a = s + (vA ? rA : 0) * ROW + 1;   // tail-safe: row 0 valid
    const float* b = s + (vB ? rB : 0) * ROW + 1;

    u64 u[M];
    #pragma unroll
    for (int i = 0; i < M; ++i) u[i] = pk2(a[i], b[i]);

    // ---- scaled downward recursion, both rows per f32x2 op ----
    u64 D = pk2(1.0f, 1.0f);
    float mA = 0.0f, mB = 0.0f;
    #pragma unroll
    for (int m = M; m >= 2; --m) {
        float umA, umB, DA, DB;
        upk2(u[m - 1], umA, umB);
        upk2(D, DA, DB);
        float kA = umA * __fdividef(1.0f, DA);
        float kB = umB * __fdividef(1.0f, DB);
        mA = fmaxf(mA, fabsf(kA));
        mB = fmaxf(mB, fabsf(kB));
        u64 nk = pk2(-kA, -kB);
        D = fma2(nk, u[m - 1], D);       // D *= (1 - k^2), both rows
        #pragma unroll
        for (int i = 0; 2 * i <= m - 2; ++i) {
            int j = m - 2 - i;
            u64 ui = u[i], uj = u[j];
            if (i < j) {
                u[i] = fma2(nk, uj, ui);
                u[j] = fma2(nk, ui, uj);
            } else {
                u[i] = fma2(nk, ui, ui);
            }
        }
    }
    {   // k_1 = u[0]/D
        float u0A, u0B, DA, DB;
        upk2(u[0], u0A, u0B);
        upk2(D, DA, DB);
        mA = fmaxf(mA, fabsf(u0A * __fdividef(1.0f, DA)));
        mB = fmaxf(mB, fabsf(u0B * __fdividef(1.0f, DB)));
    }

    // ---- rare path (also catches NaN from degenerate D) ----
    if (!(mA <= 1.0f) && vA)
        fixup_row(s + rA * ROW, out + gbase + (long long)rA * ROW);
    if (!(mB <= 1.0f) && vB)
        fixup_row(s + rB * ROW, out + gbase + (long long)rB * ROW);
}

extern "C" void kernel_launch(void* const* d_in, const int* in_sizes, int n_in,
                              void* d_out, int out_size)
{
    const float* a = (const float*)d_in[0];
    float* out = (float*)d_out;
    int B = in_sizes[0] / ROW;
    int grid = (B + ROWS_PER_BLK - 1) / ROWS_PER_BLK;
    lpc_stability_kernel<<<grid, THREADS>>>(a, out, B);
}

// round 6
// speedup vs baseline: 1.1624x; 1.1624x over previous
#include <cuda_runtime.h>

// Division-free scaled downward Levinson as a CLIP DETECTOR (1 row/thread):
//   u_i = c_i * D,  D = prod(1 - k^2)
//   k = u[m-1]*rcp(D);  D -= k*u[m-1];  u_i -= k*u_j     (1 FMA per element)
// If no |k| > 1 (BOUND = 1-1e-16 rounds to 1.0f), the PARCOR->LPC round
// trip is the identity and out == in, which was already streamed to GMEM
// during staging. Clipped / degenerate rows (incl. NaN from D underflow)
// take the exact textbook path in a __noinline__ fixup so its register
// pressure never touches the hot path.
//
// __launch_bounds__(256, 6) caps regs at ~42 -> ~48 resident warps/SM to
// hide the 23-stage RCP->FMA dependency chain (latency-bound per R4/R5).

#define M 24
#define ROW 25
#define ROWS_PER_BLK 256
#define ELEMS (ROWS_PER_BLK * ROW)   // 6400 floats per block
#define VECS  (ELEMS / 4)            // 1600 float4 per block

// Exact per-row path: true divides, clamp, upward recursion, overwrite row.
__device__ __noinline__ void fixup_row(const float* __restrict__ srow,
                                       float* __restrict__ orow)
{
    float c[M];
    #pragma unroll
    for (int i = 0; i < M; ++i) c[i] = srow[i + 1];

    #pragma unroll
    for (int m = M; m >= 2; --m) {
        float k   = c[m - 1];
        float inv = __fdividef(1.0f, 1.0f - k * k);
        #pragma unroll
        for (int i = 0; 2 * i <= m - 2; ++i) {
            int j = m - 2 - i;
            float ci = c[i], cj = c[j];
            if (i < j) {
                c[i] = fmaf(-k, cj, ci) * inv;
                c[j] = fmaf(-k, ci, cj) * inv;
            } else {
                c[i] = fmaf(-k, ci, ci) * inv;
            }
        }
    }
    #pragma unroll
    for (int i = 0; i < M; ++i)
        c[i] = fminf(fmaxf(c[i], -1.0f), 1.0f);

    #pragma unroll
    for (int m = 2; m <= M; ++m) {
        float km = c[m - 1];
        #pragma unroll
        for (int i = 0; 2 * i <= m - 2; ++i) {
            int j = m - 2 - i;
            float ci = c[i], cj = c[j];
            if (i < j) {
                c[i] = fmaf(km, cj, ci);
                c[j] = fmaf(km, ci, cj);
            } else {
                c[i] = fmaf(km, ci, ci);
            }
        }
    }
    #pragma unroll
    for (int i = 0; i < M; ++i) orow[i + 1] = c[i];
    // orow[0] (gain K) already correct from the bulk copy
}

__global__ __launch_bounds__(ROWS_PER_BLK, 6)
void lpc_stability_kernel(const float* __restrict__ in, float* __restrict__ out, int B)
{
    __shared__ float s[ELEMS];

    const int tid   = threadIdx.x;
    const int rbase = blockIdx.x * ROWS_PER_BLK;
    const long long gbase = (long long)blockIdx.x * ELEMS;
    const int nrows = min(ROWS_PER_BLK, B - rbase);

    if (nrows == ROWS_PER_BLK) {
        const float4* __restrict__ g4 = (const float4*)(in + gbase);
        float4* __restrict__ o4 = (float4*)(out + gbase);
        float4* s4 = (float4*)s;
        #pragma unroll
        for (int i = 0; i < 7; ++i) {
            int idx = tid + i * ROWS_PER_BLK;
            if (idx < VECS) {
                float4 v = g4[idx];
                o4[idx] = v;      // commit output immediately (common path)
                s4[idx] = v;      // stage for the detector
            }
        }
    } else {
        int nelems = nrows * ROW;
        for (int idx = tid; idx < nelems; idx += ROWS_PER_BLK) {
            float v = in[gbase + idx];
            out[gbase + idx] = v;
            s[idx] = v;
        }
    }
    __syncthreads();   // orders bulk stores before fixup stores; smem ready

    if (tid < nrows) {
        const float* row = &s[tid * ROW];
        float u[M];
        #pragma unroll
        for (int i = 0; i < M; ++i) u[i] = row[i + 1];

        // ---- scaled downward recursion (detector) ----
        float D = 1.0f;
        float maxa = 0.0f;
        #pragma unroll
        for (int m = M; m >= 2; --m) {
            float um = u[m - 1];
            float k  = um * __fdividef(1.0f, D);
            maxa = fmaxf(maxa, fabsf(k));
            D = fmaf(-k, um, D);                 // D *= (1 - k^2)
            #pragma unroll
            for (int i = 0; 2 * i <= m - 2; ++i) {
                int j = m - 2 - i;
                float ui = u[i];
                float uj = u[j];
                if (i < j) {
                    u[i] = fmaf(-k, uj, ui);
                    u[j] = fmaf(-k, ui, uj);
                } else {
                    u[i] = fmaf(-k, ui, ui);
                }
            }
        }
        maxa = fmaxf(maxa, fabsf(u[0] * __fdividef(1.0f, D)));   // k_1

        // ---- rare path (also catches NaN from degenerate D) ----
        if (!(maxa <= 1.0f))
            fixup_row(row, out + gbase + (long long)tid * ROW);
    }
}

extern "C" void kernel_launch(void* const* d_in, const int* in_sizes, int n_in,
                              void* d_out, int out_size)
{
    const float* a = (const float*)d_in[0];
    float* out = (float*)d_out;
    int B = in_sizes[0] / ROW;
    int grid = (B + ROWS_PER_BLK - 1) / ROWS_PER_BLK;
    lpc_stability_kernel<<<grid, ROWS_PER_BLK>>>(a, out, B);
}